// round 11
// baseline (speedup 1.0000x reference)
#include <cuda_runtime.h>

// Closed-form symmetry constraint:
// Per (batch row, class c in {0,1,2}) group of size m with u = x - 0.5:
//   sum_{i<j} (u_i+u_j)^2 = (m-2)*Su2 + Su^2
//   sum_{i<j} (y_i-y_j)^2 = m*Sy2 - Sy^2
//   pairs = m*(m-1)/2
// Output = total / max(count, 1)
//
// 128 blocks x 512 threads: 2 rows/block (8 warps/row), 2 elements/thread
// (one int2 class load + one float4 keypoint load -> 2 independent LDGs).
// 128 SMs at 4 warps/SMSP: per-SMSP issue load ~740 slots (vs ~1040 in the
// 64x512 version) with the same latency-hiding depth. Counts via ballot+popc;
// 12 float moments butterfly-reduced; block-level closed-form finalize;
// global float atomics + done-counter finalize (single graph node).

__device__ float g_total;
__device__ float g_count;
__device__ unsigned int g_done;

__global__ void __launch_bounds__(512)
sym_flat_kernel(const float* __restrict__ kp,   // [B, N, 2]
                const int*   __restrict__ cls,  // [B, N]
                float* __restrict__ out)
{
    const int tid  = threadIdx.x;
    const int wid  = tid >> 5;          // 0..15
    const int lane = tid & 31;
    const int rowInBlk = wid >> 3;      // 0..1  (8 warps per row)
    const int b        = blockIdx.x * 2 + rowInBlk;
    const int pair     = ((wid & 7) << 5) | lane;     // 0..255 (elem pair in row)
    const size_t gpair = (size_t)b * 256 + pair;

    // 2 independent wide loads, issued back-to-back.
    const int2   c2 = reinterpret_cast<const int2*>(cls)[gpair];
    const float4 p  = reinterpret_cast<const float4*>(kp)[gpair];  // (x0,y0,x1,y1)

    float su[3]  = {0.f, 0.f, 0.f};
    float su2[3] = {0.f, 0.f, 0.f};
    float sy[3]  = {0.f, 0.f, 0.f};
    float sy2[3] = {0.f, 0.f, 0.f};

    // Mask-FFMA accumulation (compile-time class indices only).
    {
        const int   cc[2] = {c2.x, c2.y};
        const float xs[2] = {p.x, p.z};
        const float ys[2] = {p.y, p.w};
        #pragma unroll
        for (int e = 0; e < 2; e++) {
            const float u  = xs[e] - 0.5f;
            const float uu = u * u;
            const float y  = ys[e];
            const float yy = y * y;
            #pragma unroll
            for (int k = 0; k < 3; k++) {
                const float mk = (cc[e] == k) ? 1.f : 0.f;
                su[k]  = fmaf(mk, u,  su[k]);
                su2[k] = fmaf(mk, uu, su2[k]);
                sy[k]  = fmaf(mk, y,  sy[k]);
                sy2[k] = fmaf(mk, yy, sy2[k]);
            }
        }
    }

    // Warp-uniform class counts via ballot+popc.
    int cnt[3];
    #pragma unroll
    for (int k = 0; k < 3; k++) {
        cnt[k] = __popc(__ballot_sync(0xFFFFFFFFu, c2.x == k))
               + __popc(__ballot_sync(0xFFFFFFFFu, c2.y == k));
    }

    // Butterfly-reduce the 12 float moments across the warp.
    #pragma unroll
    for (int off = 16; off > 0; off >>= 1) {
        #pragma unroll
        for (int k = 0; k < 3; k++) {
            su[k]  += __shfl_xor_sync(0xFFFFFFFFu, su[k],  off);
            su2[k] += __shfl_xor_sync(0xFFFFFFFFu, su2[k], off);
            sy[k]  += __shfl_xor_sync(0xFFFFFFFFu, sy[k],  off);
            sy2[k] += __shfl_xor_sync(0xFFFFFFFFu, sy2[k], off);
        }
    }

    // Per-warp partials: 12 floats + 3 counts (as float).
    __shared__ float s[16][16];
    if (lane == 0) {
        #pragma unroll
        for (int k = 0; k < 3; k++) {
            s[wid][k * 5 + 0] = su[k];
            s[wid][k * 5 + 1] = su2[k];
            s[wid][k * 5 + 2] = sy[k];
            s[wid][k * 5 + 3] = sy2[k];
            s[wid][k * 5 + 4] = (float)cnt[k];
        }
    }
    __syncthreads();

    // Threads 0..1 finalize one row each (combine 8 warps, closed form).
    __shared__ float2 rowRes[2];
    if (tid < 2) {
        const int base = tid * 8;
        float tot = 0.f, count = 0.f;
        #pragma unroll
        for (int k = 0; k < 3; k++) {
            float Su = 0.f, Su2 = 0.f, Sy = 0.f, Sy2 = 0.f, m = 0.f;
            #pragma unroll
            for (int w = 0; w < 8; w++) {
                Su  += s[base + w][k * 5 + 0];
                Su2 += s[base + w][k * 5 + 1];
                Sy  += s[base + w][k * 5 + 2];
                Sy2 += s[base + w][k * 5 + 3];
                m   += s[base + w][k * 5 + 4];
            }
            tot   += (m - 2.f) * Su2 + Su * Su + m * Sy2 - Sy * Sy;
            count += 0.5f * m * (m - 1.f);
        }
        rowRes[tid] = make_float2(tot, count);
    }
    __syncthreads();

    if (tid == 0) {
        const float tot   = rowRes[0].x + rowRes[1].x;
        const float count = rowRes[0].y + rowRes[1].y;

        atomicAdd(&g_total, tot);    // return unused -> REDG
        atomicAdd(&g_count, count);  // return unused -> REDG
        __threadfence();
        const unsigned int done = atomicAdd(&g_done, 1u);
        if (done == gridDim.x - 1) {
            // Last block: all prior atomics visible (fenced above).
            const float t = *((volatile float*)&g_total);
            const float c = *((volatile float*)&g_count);
            out[0] = t / fmaxf(c, 1.f);
            // Self-reset so each graph replay starts clean (deterministic).
            *((volatile float*)&g_total) = 0.f;
            *((volatile float*)&g_count) = 0.f;
            __threadfence();
            *((volatile unsigned int*)&g_done) = 0u;
        }
    }
}

extern "C" void kernel_launch(void* const* d_in, const int* in_sizes, int n_in,
                              void* d_out, int out_size)
{
    const float* kp  = (const float*)d_in[0];   // [B, N, 2] float32
    const int*   cls = (const int*)d_in[1];     // [B, N] int32
    float* out = (float*)d_out;

    const int BN = in_sizes[1];   // B * N = 131072
    const int B  = BN / 512;      // 256
    sym_flat_kernel<<<B / 2, 512>>>(kp, cls, out);
}